// round 1
// baseline (speedup 1.0000x reference)
#include <cuda_runtime.h>
#include <cuda_bf16.h>
#include <math.h>

// ---------------- problem constants ----------------
#define Bb     4
#define Nn     4096
#define Dm     1024
#define Hh     16
#define DHe    64
#define DFFe   4096
#define Mf     256
#define BH     (Bb*Hh)          // 64
#define Tt     (Bb*Nn)          // 16384
#define NORMF  0.3535533905932738f   // 64^-0.25
#define RATIOF 0.0625f               // 256^-0.5
#define EPSKF  1e-4f
#define LNEPS  1e-5f

// ---------------- scratch (device globals, no allocs) ----------------
__device__ float g_q   [Tt*Dm];
__device__ float g_k   [Tt*Dm];
__device__ float g_v   [Tt*Dm];
__device__ float g_qp  [BH*Nn*Mf];    // 64 MB
__device__ float g_kp  [BH*Nn*Mf];    // xp in passA, kp after passB
__device__ float g_kdiag[BH*Nn];
__device__ float g_kstab[BH];
__device__ float g_ksum[BH*Mf];
__device__ float g_ctx [BH*Mf*DHe];
__device__ float g_attn[Tt*Dm];
__device__ float g_y   [Tt*Dm];       // Wo output / FFN2 output
__device__ float g_x1  [Tt*Dm];       // post-LN1
__device__ float g_ffh [Tt*DFFe];     // 256 MB

// ---------------- helpers ----------------
__device__ __forceinline__ void atomicMaxF(float* addr, float v) {
    int old = __float_as_int(*addr);
    while (__int_as_float(old) < v) {
        int assumed = old;
        old = atomicCAS((int*)addr, assumed, __float_as_int(v));
        if (old == assumed) break;
    }
}

// ---------------- SGEMM NT: C[M,N] = A[M,K] @ W[N,K]^T + bias (opt relu) ----
// BM=BN=128, BK=8, 256 threads, 8x8 per-thread microtile.
__global__ __launch_bounds__(256)
void sgemm_nt(const float* __restrict__ A, const float* __restrict__ W,
              const float* __restrict__ bias, float* __restrict__ C,
              int M, int N, int K, int relu)
{
    __shared__ float As[8*132];
    __shared__ float Ws[8*132];

    const int tid = threadIdx.x;
    const int tx  = tid & 15;      // N dir
    const int ty  = tid >> 4;      // M dir
    const int rowL = tid >> 1;     // 0..127
    const int kpart = tid & 1;     // 0/1

    const int blockM = blockIdx.y * 128;
    const int blockN = blockIdx.x * 128;

    const float* Aptr = A + (size_t)(blockM + rowL) * K + kpart*4;
    const float* Wptr = W + (size_t)(blockN + rowL) * K + kpart*4;

    float acc[8][8];
    #pragma unroll
    for (int i = 0; i < 8; i++)
        #pragma unroll
        for (int j = 0; j < 8; j++) acc[i][j] = 0.f;

    for (int k0 = 0; k0 < K; k0 += 8) {
        float4 a4 = *(const float4*)(Aptr + k0);
        float4 w4 = *(const float4*)(Wptr + k0);
        float av[4] = {a4.x, a4.y, a4.z, a4.w};
        float wv[4] = {w4.x, w4.y, w4.z, w4.w};
        #pragma unroll
        for (int j = 0; j < 4; j++) {
            As[(kpart*4 + j)*132 + rowL] = av[j];
            Ws[(kpart*4 + j)*132 + rowL] = wv[j];
        }
        __syncthreads();
        #pragma unroll
        for (int kk = 0; kk < 8; kk++) {
            float4 a0 = *(const float4*)&As[kk*132 + ty*8];
            float4 a1 = *(const float4*)&As[kk*132 + ty*8 + 4];
            float4 b0 = *(const float4*)&Ws[kk*132 + tx*8];
            float4 b1 = *(const float4*)&Ws[kk*132 + tx*8 + 4];
            float ar[8] = {a0.x,a0.y,a0.z,a0.w,a1.x,a1.y,a1.z,a1.w};
            float br[8] = {b0.x,b0.y,b0.z,b0.w,b1.x,b1.y,b1.z,b1.w};
            #pragma unroll
            for (int i = 0; i < 8; i++)
                #pragma unroll
                for (int j = 0; j < 8; j++)
                    acc[i][j] += ar[i]*br[j];
        }
        __syncthreads();
    }

    const int gc = blockN + tx*8;
    float4 bia0 = *(const float4*)(bias + gc);
    float4 bia1 = *(const float4*)(bias + gc + 4);
    #pragma unroll
    for (int i = 0; i < 8; i++) {
        int gr = blockM + ty*8 + i;
        float o[8];
        o[0]=acc[i][0]+bia0.x; o[1]=acc[i][1]+bia0.y; o[2]=acc[i][2]+bia0.z; o[3]=acc[i][3]+bia0.w;
        o[4]=acc[i][4]+bia1.x; o[5]=acc[i][5]+bia1.y; o[6]=acc[i][6]+bia1.z; o[7]=acc[i][7]+bia1.w;
        if (relu) {
            #pragma unroll
            for (int j = 0; j < 8; j++) o[j] = fmaxf(o[j], 0.f);
        }
        float* cp = C + (size_t)gr * N + gc;
        *(float4*)cp       = make_float4(o[0],o[1],o[2],o[3]);
        *(float4*)(cp + 4) = make_float4(o[4],o[5],o[6],o[7]);
    }
}

// ---------------- init kstab ----------------
__global__ void init_kstab() {
    if (threadIdx.x < BH) g_kstab[threadIdx.x] = -INFINITY;
}

// ---------------- feature map: Q (per-row stabilizer) ----------------
// rows = bh*Nn + n ; x = q[(b*Nn+n)*Dm + h*DHe + d]
#define FEAT_ROWS_PB 64
__global__ __launch_bounds__(256)
void feat_q_kernel(const float* __restrict__ proj)
{
    extern __shared__ float sm[];
    float* projT = sm;               // [64][256] : projT[d*256+m]
    float* xs    = sm + 64*256;      // 64
    float* red   = xs + 64;          // 8
    float* bc    = red + 8;          // 1

    const int tid = threadIdx.x;
    for (int i = tid; i < 64*256; i += 256) {
        int d = i >> 8, m = i & 255;
        projT[i] = proj[m*64 + d];
    }
    __syncthreads();

    const int lane = tid & 31, wid = tid >> 5;
    const int row0 = blockIdx.x * FEAT_ROWS_PB;

    for (int r = 0; r < FEAT_ROWS_PB; r++) {
        __syncthreads();
        const int row = row0 + r;
        const int bh = row >> 12, n = row & (Nn-1);
        const int b = bh >> 4, h = bh & 15;
        const float* x = g_q + (size_t)(b*Nn + n)*Dm + h*DHe;
        if (tid < 64) xs[tid] = x[tid] * NORMF;
        __syncthreads();

        float acc = 0.f, sq = 0.f;
        #pragma unroll
        for (int d = 0; d < 64; d++) {
            float xv = xs[d];
            acc += xv * projT[d*256 + tid];
            sq  += xv * xv;
        }
        float diag = 0.5f * sq;

        float mx = acc;
        #pragma unroll
        for (int off = 16; off; off >>= 1)
            mx = fmaxf(mx, __shfl_xor_sync(0xffffffffu, mx, off));
        if (lane == 0) red[wid] = mx;
        __syncthreads();
        if (tid == 0) {
            float mm = red[0];
            #pragma unroll
            for (int i = 1; i < 8; i++) mm = fmaxf(mm, red[i]);
            bc[0] = mm;
        }
        __syncthreads();
        float stab = bc[0];
        g_qp[(size_t)row*Mf + tid] = RATIOF * (expf(acc - diag - stab) + EPSKF);
    }
}

// ---------------- feature map: K pass A (xp + diag + global max) ----------
__global__ __launch_bounds__(256)
void feat_kA_kernel(const float* __restrict__ proj)
{
    extern __shared__ float sm[];
    float* projT = sm;
    float* xs    = sm + 64*256;
    float* red   = xs + 64;

    const int tid = threadIdx.x;
    for (int i = tid; i < 64*256; i += 256) {
        int d = i >> 8, m = i & 255;
        projT[i] = proj[m*64 + d];
    }
    __syncthreads();

    const int lane = tid & 31, wid = tid >> 5;
    const int row0 = blockIdx.x * FEAT_ROWS_PB;
    const int bh = row0 >> 12;   // 64 rows never cross bh (64 | 4096)
    float runmax = -INFINITY;

    for (int r = 0; r < FEAT_ROWS_PB; r++) {
        __syncthreads();
        const int row = row0 + r;
        const int n = row & (Nn-1);
        const int b = bh >> 4, h = bh & 15;
        const float* x = g_k + (size_t)(b*Nn + n)*Dm + h*DHe;
        if (tid < 64) xs[tid] = x[tid] * NORMF;
        __syncthreads();

        float acc = 0.f, sq = 0.f;
        #pragma unroll
        for (int d = 0; d < 64; d++) {
            float xv = xs[d];
            acc += xv * projT[d*256 + tid];
            sq  += xv * xv;
        }
        g_kp[(size_t)row*Mf + tid] = acc;      // store raw xp
        if (tid == 0) g_kdiag[row] = 0.5f * sq;
        runmax = fmaxf(runmax, acc);
    }
    // block max -> one atomic
    #pragma unroll
    for (int off = 16; off; off >>= 1)
        runmax = fmaxf(runmax, __shfl_xor_sync(0xffffffffu, runmax, off));
    if (lane == 0) red[wid] = runmax;
    __syncthreads();
    if (tid == 0) {
        float mm = red[0];
        #pragma unroll
        for (int i = 1; i < 8; i++) mm = fmaxf(mm, red[i]);
        atomicMaxF(&g_kstab[bh], mm);
    }
}

// ---------------- feature map: K pass B (exp with global stab) ------------
__global__ __launch_bounds__(256)
void feat_kB_kernel()
{
    size_t idx = (size_t)blockIdx.x * 256 + threadIdx.x;  // < BH*Nn*Mf
    int row = (int)(idx >> 8);
    int bh  = row >> 12;
    float xp = g_kp[idx];
    g_kp[idx] = RATIOF * (expf(xp - g_kdiag[row] - g_kstab[bh]) + EPSKF);
}

// ---------------- ksum[bh][m] = sum_n kp[bh][n][m] ----------------
__global__ __launch_bounds__(256)
void ksum_kernel()
{
    const int bh = blockIdx.x;
    const int m = threadIdx.x;
    const float* kp = g_kp + (size_t)bh * Nn * Mf + m;
    float acc = 0.f;
    #pragma unroll 8
    for (int n = 0; n < Nn; n++) acc += kp[(size_t)n * Mf];
    g_ksum[bh*Mf + m] = acc;
}

// ---------------- ctx[bh][m][d] = sum_n kp[bh][n][m] * v[b,n,h,d] ----------
__global__ __launch_bounds__(256)
void ctx_kernel()
{
    __shared__ float kpc[32][64];
    __shared__ float vc [32][64];

    const int bh = blockIdx.x;            // 0..63
    const int mtile = blockIdx.y;         // 0..3 (64 m each)
    const int b = bh >> 4, h = bh & 15;
    const int tid = threadIdx.x;
    const int tx = tid & 15;              // d dir (4 each)
    const int ty = tid >> 4;              // m dir (4 each)

    float acc[4][4];
    #pragma unroll
    for (int i = 0; i < 4; i++)
        #pragma unroll
        for (int j = 0; j < 4; j++) acc[i][j] = 0.f;

    const float* kpBase = g_kp + (size_t)bh * Nn * Mf + mtile*64;
    const float* vBase  = g_v  + (size_t)b * Nn * Dm + h*DHe;

    for (int n0 = 0; n0 < Nn; n0 += 32) {
        #pragma unroll
        for (int it = 0; it < 8; it++) {
            int j = it*256 + tid;
            int nn = j >> 6, c = j & 63;
            kpc[nn][c] = kpBase[(size_t)(n0+nn)*Mf + c];
            vc [nn][c] = vBase [(size_t)(n0+nn)*Dm + c];
        }
        __syncthreads();
        #pragma unroll
        for (int nn = 0; nn < 32; nn++) {
            float4 kf = *(const float4*)&kpc[nn][ty*4];
            float4 vf = *(const float4*)&vc [nn][tx*4];
            float kr[4] = {kf.x,kf.y,kf.z,kf.w};
            float vr[4] = {vf.x,vf.y,vf.z,vf.w};
            #pragma unroll
            for (int i = 0; i < 4; i++)
                #pragma unroll
                for (int j = 0; j < 4; j++)
                    acc[i][j] += kr[i]*vr[j];
        }
        __syncthreads();
    }
    #pragma unroll
    for (int i = 0; i < 4; i++) {
        int m = mtile*64 + ty*4 + i;
        float* cp = g_ctx + (size_t)bh*Mf*DHe + m*DHe + tx*4;
        *(float4*)cp = make_float4(acc[i][0],acc[i][1],acc[i][2],acc[i][3]);
    }
}

// ---------------- out = (qp @ ctx) / (qp . ksum), write to attn layout -----
__global__ __launch_bounds__(256)
void attnout_kernel()
{
    extern __shared__ float sm[];
    float* ctxT  = sm;                 // [64][260] padded, ctxT[d*260+m]
    float* ksum_s= sm + 64*260;        // 256
    float* qps   = ksum_s + 256;       // 4*256

    const int ntile = blockIdx.x;      // 0..63 (64 tokens each)
    const int bh    = blockIdx.y;      // 0..63
    const int b = bh >> 4, h = bh & 15;
    const int tid = threadIdx.x;

    for (int j = tid; j < Mf*DHe; j += 256) {
        int m = j >> 6, d = j & 63;
        ctxT[d*260 + m] = g_ctx[(size_t)bh*Mf*DHe + j];
    }
    ksum_s[tid] = g_ksum[bh*Mf + tid];
    __syncthreads();

    const int d   = tid & 63;
    const int tok = tid >> 6;
    const float4* ct4 = (const float4*)(ctxT + d*260);
    const float4* ks4 = (const float4*)ksum_s;

    for (int gIt = 0; gIt < 16; gIt++) {
        int nbase = ntile*64 + gIt*4;
        #pragma unroll
        for (int it = 0; it < 4; it++) {
            int j = it*256 + tid;
            int tk = j >> 8, mm = j & 255;
            qps[j] = g_qp[((size_t)bh*Nn + nbase + tk)*Mf + mm];
        }
        __syncthreads();

        const float4* qv4 = (const float4*)(qps + tok*256);
        float acc = 0.f, den = 0.f;
        #pragma unroll 8
        for (int mq = 0; mq < 64; mq++) {
            float4 qf = qv4[mq];
            float4 cf = ct4[mq];
            float4 kf = ks4[mq];
            acc += qf.x*cf.x + qf.y*cf.y + qf.z*cf.z + qf.w*cf.w;
            den += qf.x*kf.x + qf.y*kf.y + qf.z*kf.z + qf.w*kf.w;
        }
        int n = nbase + tok;
        g_attn[(size_t)(b*Nn + n)*Dm + h*DHe + d] = acc / den;
        __syncthreads();
    }
}

// ---------------- LayerNorm(a + b) * g + be ----------------
__global__ __launch_bounds__(256)
void ln_kernel(const float* __restrict__ A, const float* __restrict__ Bc,
               const float* __restrict__ g, const float* __restrict__ be,
               float* __restrict__ out)
{
    __shared__ float s1s[8], s2s[8], bc[2];
    const int row = blockIdx.x;
    const int tid = threadIdx.x;
    const int lane = tid & 31, wid = tid >> 5;

    const float4* a4 = (const float4*)(A  + (size_t)row*Dm);
    const float4* b4 = (const float4*)(Bc + (size_t)row*Dm);
    float4 va = a4[tid], vb = b4[tid];
    float4 v = make_float4(va.x+vb.x, va.y+vb.y, va.z+vb.z, va.w+vb.w);

    float s1 = v.x+v.y+v.z+v.w;
    float s2 = v.x*v.x+v.y*v.y+v.z*v.z+v.w*v.w;
    #pragma unroll
    for (int off = 16; off; off >>= 1) {
        s1 += __shfl_xor_sync(0xffffffffu, s1, off);
        s2 += __shfl_xor_sync(0xffffffffu, s2, off);
    }
    if (lane == 0) { s1s[wid] = s1; s2s[wid] = s2; }
    __syncthreads();
    if (tid == 0) {
        float S1 = 0.f, S2 = 0.f;
        #pragma unroll
        for (int i = 0; i < 8; i++) { S1 += s1s[i]; S2 += s2s[i]; }
        float mu = S1 * (1.f/Dm);
        float var = S2 * (1.f/Dm) - mu*mu;
        bc[0] = mu;
        bc[1] = rsqrtf(var + LNEPS);
    }
    __syncthreads();
    float mu = bc[0], rstd = bc[1];

    float4 gg = ((const float4*)g)[tid];
    float4 bb = ((const float4*)be)[tid];
    float4 o = make_float4((v.x-mu)*rstd*gg.x + bb.x,
                           (v.y-mu)*rstd*gg.y + bb.y,
                           (v.z-mu)*rstd*gg.z + bb.z,
                           (v.w-mu)*rstd*gg.w + bb.w);
    ((float4*)(out + (size_t)row*Dm))[tid] = o;
}

// ---------------- host ----------------
extern "C" void kernel_launch(void* const* d_in, const int* in_sizes, int n_in,
                              void* d_out, int out_size)
{
    const float* video = (const float*)d_in[0];
    const float* Wq    = (const float*)d_in[1];
    const float* bq    = (const float*)d_in[2];
    const float* Wk    = (const float*)d_in[3];
    const float* bk    = (const float*)d_in[4];
    const float* Wv    = (const float*)d_in[5];
    const float* bv    = (const float*)d_in[6];
    const float* Wo    = (const float*)d_in[7];
    const float* bo    = (const float*)d_in[8];
    const float* proj  = (const float*)d_in[9];
    const float* W1    = (const float*)d_in[10];
    const float* b1    = (const float*)d_in[11];
    const float* W2    = (const float*)d_in[12];
    const float* b2    = (const float*)d_in[13];
    const float* g2    = (const float*)d_in[14];
    const float* be2   = (const float*)d_in[15];
    const float* g3    = (const float*)d_in[16];
    const float* be3   = (const float*)d_in[17];
    float* out = (float*)d_out;

    float *q, *k, *v, *attn, *y, *x1, *ffh;
    cudaGetSymbolAddress((void**)&q,    g_q);
    cudaGetSymbolAddress((void**)&k,    g_k);
    cudaGetSymbolAddress((void**)&v,    g_v);
    cudaGetSymbolAddress((void**)&attn, g_attn);
    cudaGetSymbolAddress((void**)&y,    g_y);
    cudaGetSymbolAddress((void**)&x1,   g_x1);
    cudaGetSymbolAddress((void**)&ffh,  g_ffh);

    const int featSmem = (64*256 + 64 + 8 + 1) * 4;
    const int outSmem  = (64*260 + 256 + 4*256) * 4;
    cudaFuncSetAttribute(feat_q_kernel,  cudaFuncAttributeMaxDynamicSharedMemorySize, featSmem);
    cudaFuncSetAttribute(feat_kA_kernel, cudaFuncAttributeMaxDynamicSharedMemorySize, featSmem);
    cudaFuncSetAttribute(attnout_kernel, cudaFuncAttributeMaxDynamicSharedMemorySize, outSmem);

    // 1. QKV projections
    dim3 gQKV(Dm/128, Tt/128);
    sgemm_nt<<<gQKV, 256>>>(video, Wq, bq, q, Tt, Dm, Dm, 0);
    sgemm_nt<<<gQKV, 256>>>(video, Wk, bk, k, Tt, Dm, Dm, 0);
    sgemm_nt<<<gQKV, 256>>>(video, Wv, bv, v, Tt, Dm, Dm, 0);

    // 2. feature maps
    init_kstab<<<1, 64>>>();
    int featBlocks = (BH*Nn) / FEAT_ROWS_PB;  // 4096
    feat_q_kernel <<<featBlocks, 256, featSmem>>>(proj);
    feat_kA_kernel<<<featBlocks, 256, featSmem>>>(proj);
    feat_kB_kernel<<<(BH*(size_t)Nn*Mf)/256, 256>>>();

    // 3. linear attention
    ksum_kernel<<<BH, 256>>>();
    ctx_kernel<<<dim3(BH, Mf/64), 256>>>();
    attnout_kernel<<<dim3(Nn/64, BH), 256, outSmem>>>();

    // 4. output projection + residual LN
    sgemm_nt<<<gQKV, 256>>>(attn, Wo, bo, y, Tt, Dm, Dm, 0);
    ln_kernel<<<Tt, 256>>>(video, y, g2, be2, x1);

    // 5. FFN
    sgemm_nt<<<dim3(DFFe/128, Tt/128), 256>>>(x1, W1, b1, ffh, Tt, DFFe, Dm, 1);
    sgemm_nt<<<dim3(Dm/128, Tt/128), 256>>>(ffh, W2, b2, y, Tt, Dm, DFFe, 0);
    ln_kernel<<<Tt, 256>>>(x1, y, g3, be3, out);
}

// round 3
// speedup vs baseline: 1.9613x; 1.9613x over previous
#include <cuda_runtime.h>
#include <cuda_bf16.h>
#include <math.h>
#include <stdint.h>

// ---------------- problem constants ----------------
#define Bb     4
#define Nn     4096
#define Dm     1024
#define Hh     16
#define DHe    64
#define DFFe   4096
#define Mf     256
#define BH     (Bb*Hh)          // 64
#define Tt     (Bb*Nn)          // 16384
#define NORMF  0.3535533905932738f   // 64^-0.25
#define RATIOF 0.0625f               // 256^-0.5
#define EPSKF  1e-4f
#define LNEPS  1e-5f

// ---------------- scratch (device globals, no allocs) ----------------
__device__ float g_q   [Tt*Dm];
__device__ float g_k   [Tt*Dm];
__device__ float g_v   [Tt*Dm];
__device__ float g_qp  [BH*Nn*Mf];
__device__ float g_kp  [BH*Nn*Mf];
__device__ float g_kdiag[BH*Nn];
__device__ float g_kstab[BH];
__device__ float g_ksum[BH*Mf];
__device__ float g_ctx [BH*Mf*DHe];
__device__ float g_attn[Tt*Dm];
__device__ float g_y   [Tt*Dm];
__device__ float g_x1  [Tt*Dm];
__device__ float g_ffh [Tt*DFFe];

// ---------------- helpers ----------------
__device__ __forceinline__ uint32_t f2tf(float f){
    uint32_t r; asm("cvt.rna.tf32.f32 %0, %1;" : "=r"(r) : "f"(f)); return r;
}
__device__ __forceinline__ void mma16n8k8(float c[4], const uint32_t a[4], const uint32_t b[2]){
    asm volatile("mma.sync.aligned.m16n8k8.row.col.f32.tf32.tf32.f32 "
        "{%0,%1,%2,%3}, {%4,%5,%6,%7}, {%8,%9}, {%0,%1,%2,%3};"
        : "+f"(c[0]), "+f"(c[1]), "+f"(c[2]), "+f"(c[3])
        : "r"(a[0]), "r"(a[1]), "r"(a[2]), "r"(a[3]), "r"(b[0]), "r"(b[1]));
}
__device__ __forceinline__ void atomicMaxF(float* addr, float v) {
    int old = __float_as_int(*addr);
    while (__int_as_float(old) < v) {
        int assumed = old;
        old = atomicCAS((int*)addr, assumed, __float_as_int(v));
        if (old == assumed) break;
    }
}

// ---------------- tf32 mma.sync GEMM-NT: C[M,N]=A[M,K]@W[N,K]^T + bias -----
// BM=BN=128, BK=32, 256 threads (8 warps: 4M x 2N), warp tile 32x64.
// Double-buffered smem, stride 36 floats (conflict-free fragment loads).
#define GBM 128
#define GBN 128
#define GBK 32
#define SBUF 9216                  // floats per buffer: (128*36)*2
#define GEMM_SMEM (2*SBUF*4)       // 73728 bytes

__global__ __launch_bounds__(256)
void mma_gemm(const float* __restrict__ A, const float* __restrict__ W,
              const float* __restrict__ bias, float* __restrict__ C,
              int M, int N, int K, int relu)
{
    extern __shared__ float sm[];

    const int tid  = threadIdx.x;
    const int lane = tid & 31;
    const int w    = tid >> 5;
    const int wm   = (w & 3) * 32;       // warp M offset in tile
    const int wn   = (w >> 2) * 64;      // warp N offset in tile
    const int lr   = lane >> 2;          // 0..7
    const int lc   = lane & 3;           // 0..3

    const int blockM = blockIdx.y * GBM;
    const int blockN = blockIdx.x * GBN;

    const int row = tid >> 1;            // 0..127  (2 threads per row)
    const int q   = (tid & 1) * 4;       // float4 index pair: covers 8 floats? no ->
    // each thread loads 4 float4 (16 floats): rows (tid>>1), quarters q..q+3? rework:
    // mapping: idx = it*256 + tid; r = idx>>3 (0..127), qq = idx&7 (8 float4 per 32-float row)
    (void)row; (void)q;

    float c[2][8][4];
    #pragma unroll
    for (int i = 0; i < 2; i++)
        #pragma unroll
        for (int j = 0; j < 8; j++)
            #pragma unroll
            for (int t = 0; t < 4; t++) c[i][j][t] = 0.f;

    const int KT = K / GBK;

    float4 pa[4], pb[4];
    // ---- load tile 0 into regs ----
    #pragma unroll
    for (int it = 0; it < 4; it++) {
        int idx = it*256 + tid;
        int r = idx >> 3, qq = idx & 7;
        pa[it] = *(const float4*)(A + (size_t)(blockM + r)*K + qq*4);
        pb[it] = *(const float4*)(W + (size_t)(blockN + r)*K + qq*4);
    }
    // ---- store tile 0 ----
    {
        float* sA = sm;            float* sB = sm + 4608;
        #pragma unroll
        for (int it = 0; it < 4; it++) {
            int idx = it*256 + tid;
            int r = idx >> 3, qq = idx & 7;
            float* pA = sA + r*36 + qq*4;
            float* pB = sB + r*36 + qq*4;
            pA[0] = __uint_as_float(f2tf(pa[it].x)); pA[1] = __uint_as_float(f2tf(pa[it].y));
            pA[2] = __uint_as_float(f2tf(pa[it].z)); pA[3] = __uint_as_float(f2tf(pa[it].w));
            pB[0] = __uint_as_float(f2tf(pb[it].x)); pB[1] = __uint_as_float(f2tf(pb[it].y));
            pB[2] = __uint_as_float(f2tf(pb[it].z)); pB[3] = __uint_as_float(f2tf(pb[it].w));
        }
    }
    __syncthreads();

    for (int kt = 0; kt < KT; kt++) {
        // prefetch next tile
        if (kt + 1 < KT) {
            const float* An = A + (size_t)blockM*K + (kt+1)*GBK;
            const float* Wn = W + (size_t)blockN*K + (kt+1)*GBK;
            #pragma unroll
            for (int it = 0; it < 4; it++) {
                int idx = it*256 + tid;
                int r = idx >> 3, qq = idx & 7;
                pa[it] = *(const float4*)(An + (size_t)r*K + qq*4);
                pb[it] = *(const float4*)(Wn + (size_t)r*K + qq*4);
            }
        }

        const float* cA = sm + (kt & 1) * SBUF;
        const float* cB = cA + 4608;

        #pragma unroll
        for (int ks = 0; ks < 4; ks++) {
            const int k0 = ks * 8;
            uint32_t a[2][4], b[8][2];
            #pragma unroll
            for (int i = 0; i < 2; i++) {
                int r = wm + i*16 + lr;
                a[i][0] = __float_as_uint(cA[r*36 + k0 + lc]);
                a[i][1] = __float_as_uint(cA[(r+8)*36 + k0 + lc]);
                a[i][2] = __float_as_uint(cA[r*36 + k0 + 4 + lc]);
                a[i][3] = __float_as_uint(cA[(r+8)*36 + k0 + 4 + lc]);
            }
            #pragma unroll
            for (int j = 0; j < 8; j++) {
                int n = wn + j*8 + lr;
                b[j][0] = __float_as_uint(cB[n*36 + k0 + lc]);
                b[j][1] = __float_as_uint(cB[n*36 + k0 + 4 + lc]);
            }
            #pragma unroll
            for (int i = 0; i < 2; i++)
                #pragma unroll
                for (int j = 0; j < 8; j++)
                    mma16n8k8(c[i][j], a[i], b[j]);
        }

        // store next tile into other buffer
        if (kt + 1 < KT) {
            float* nA = sm + ((kt+1) & 1) * SBUF;
            float* nB = nA + 4608;
            #pragma unroll
            for (int it = 0; it < 4; it++) {
                int idx = it*256 + tid;
                int r = idx >> 3, qq = idx & 7;
                float* pA = nA + r*36 + qq*4;
                float* pB = nB + r*36 + qq*4;
                pA[0] = __uint_as_float(f2tf(pa[it].x)); pA[1] = __uint_as_float(f2tf(pa[it].y));
                pA[2] = __uint_as_float(f2tf(pa[it].z)); pA[3] = __uint_as_float(f2tf(pa[it].w));
                pB[0] = __uint_as_float(f2tf(pb[it].x)); pB[1] = __uint_as_float(f2tf(pb[it].y));
                pB[2] = __uint_as_float(f2tf(pb[it].z)); pB[3] = __uint_as_float(f2tf(pb[it].w));
            }
        }
        __syncthreads();
    }

    // ---- epilogue: bias (+relu), float2 stores ----
    #pragma unroll
    for (int i = 0; i < 2; i++) {
        int gr0 = blockM + wm + i*16 + lr;
        #pragma unroll
        for (int j = 0; j < 8; j++) {
            int gc = blockN + wn + j*8 + 2*lc;
            float b0 = bias[gc], b1 = bias[gc+1];
            float o0 = c[i][j][0] + b0, o1 = c[i][j][1] + b1;
            float o2 = c[i][j][2] + b0, o3 = c[i][j][3] + b1;
            if (relu) {
                o0 = fmaxf(o0, 0.f); o1 = fmaxf(o1, 0.f);
                o2 = fmaxf(o2, 0.f); o3 = fmaxf(o3, 0.f);
            }
            *(float2*)(C + (size_t)gr0*N + gc)     = make_float2(o0, o1);
            *(float2*)(C + (size_t)(gr0+8)*N + gc) = make_float2(o2, o3);
        }
    }
}

// ---------------- init kstab ----------------
__global__ void init_kstab() {
    if (threadIdx.x < BH) g_kstab[threadIdx.x] = -INFINITY;
}

// ---------------- feature map: Q (per-row stabilizer) ----------------
#define FEAT_ROWS_PB 64
__global__ __launch_bounds__(256)
void feat_q_kernel(const float* __restrict__ proj)
{
    extern __shared__ float fsm[];
    float* projT = fsm;              // [64][256]
    float* xs    = fsm + 64*256;     // 64
    float* red   = xs + 64;          // 8
    float* bc    = red + 8;          // 1

    const int tid = threadIdx.x;
    for (int i = tid; i < 64*256; i += 256) {
        int d = i >> 8, m = i & 255;
        projT[i] = proj[m*64 + d];
    }
    __syncthreads();

    const int lane = tid & 31, wid = tid >> 5;
    const int row0 = blockIdx.x * FEAT_ROWS_PB;

    for (int r = 0; r < FEAT_ROWS_PB; r++) {
        __syncthreads();
        const int row = row0 + r;
        const int bh = row >> 12, n = row & (Nn-1);
        const int b = bh >> 4, h = bh & 15;
        const float* x = g_q + (size_t)(b*Nn + n)*Dm + h*DHe;
        if (tid < 64) xs[tid] = x[tid] * NORMF;
        __syncthreads();

        float acc = 0.f, sq = 0.f;
        #pragma unroll
        for (int d = 0; d < 64; d++) {
            float xv = xs[d];
            acc += xv * projT[d*256 + tid];
            sq  += xv * xv;
        }
        float diag = 0.5f * sq;

        float mx = acc;
        #pragma unroll
        for (int off = 16; off; off >>= 1)
            mx = fmaxf(mx, __shfl_xor_sync(0xffffffffu, mx, off));
        if (lane == 0) red[wid] = mx;
        __syncthreads();
        if (tid == 0) {
            float mm = red[0];
            #pragma unroll
            for (int i = 1; i < 8; i++) mm = fmaxf(mm, red[i]);
            bc[0] = mm;
        }
        __syncthreads();
        float stab = bc[0];
        g_qp[(size_t)row*Mf + tid] = RATIOF * (expf(acc - diag - stab) + EPSKF);
    }
}

// ---------------- feature map: K pass A ----------------
__global__ __launch_bounds__(256)
void feat_kA_kernel(const float* __restrict__ proj)
{
    extern __shared__ float fsm[];
    float* projT = fsm;
    float* xs    = fsm + 64*256;
    float* red   = xs + 64;

    const int tid = threadIdx.x;
    for (int i = tid; i < 64*256; i += 256) {
        int d = i >> 8, m = i & 255;
        projT[i] = proj[m*64 + d];
    }
    __syncthreads();

    const int lane = tid & 31, wid = tid >> 5;
    const int row0 = blockIdx.x * FEAT_ROWS_PB;
    const int bh = row0 >> 12;
    float runmax = -INFINITY;

    for (int r = 0; r < FEAT_ROWS_PB; r++) {
        __syncthreads();
        const int row = row0 + r;
        const int n = row & (Nn-1);
        const int b = bh >> 4, h = bh & 15;
        const float* x = g_k + (size_t)(b*Nn + n)*Dm + h*DHe;
        if (tid < 64) xs[tid] = x[tid] * NORMF;
        __syncthreads();

        float acc = 0.f, sq = 0.f;
        #pragma unroll
        for (int d = 0; d < 64; d++) {
            float xv = xs[d];
            acc += xv * projT[d*256 + tid];
            sq  += xv * xv;
        }
        g_kp[(size_t)row*Mf + tid] = acc;
        if (tid == 0) g_kdiag[row] = 0.5f * sq;
        runmax = fmaxf(runmax, acc);
    }
    #pragma unroll
    for (int off = 16; off; off >>= 1)
        runmax = fmaxf(runmax, __shfl_xor_sync(0xffffffffu, runmax, off));
    if (lane == 0) red[wid] = runmax;
    __syncthreads();
    if (tid == 0) {
        float mm = red[0];
        #pragma unroll
        for (int i = 1; i < 8; i++) mm = fmaxf(mm, red[i]);
        atomicMaxF(&g_kstab[bh], mm);
    }
}

// ---------------- feature map: K pass B ----------------
__global__ __launch_bounds__(256)
void feat_kB_kernel()
{
    size_t idx = (size_t)blockIdx.x * 256 + threadIdx.x;
    int row = (int)(idx >> 8);
    int bh  = row >> 12;
    float xp = g_kp[idx];
    g_kp[idx] = RATIOF * (expf(xp - g_kdiag[row] - g_kstab[bh]) + EPSKF);
}

// ---------------- ksum ----------------
__global__ __launch_bounds__(256)
void ksum_kernel()
{
    const int bh = blockIdx.x;
    const int m = threadIdx.x;
    const float* kp = g_kp + (size_t)bh * Nn * Mf + m;
    float acc = 0.f;
    #pragma unroll 8
    for (int n = 0; n < Nn; n++) acc += kp[(size_t)n * Mf];
    g_ksum[bh*Mf + m] = acc;
}

// ---------------- ctx[bh][m][d] = sum_n kp * v ----------------
__global__ __launch_bounds__(256)
void ctx_kernel()
{
    __shared__ float kpc[32][64];
    __shared__ float vc [32][64];

    const int bh = blockIdx.x;
    const int mtile = blockIdx.y;
    const int b = bh >> 4, h = bh & 15;
    const int tid = threadIdx.x;
    const int tx = tid & 15;
    const int ty = tid >> 4;

    float acc[4][4];
    #pragma unroll
    for (int i = 0; i < 4; i++)
        #pragma unroll
        for (int j = 0; j < 4; j++) acc[i][j] = 0.f;

    const float* kpBase = g_kp + (size_t)bh * Nn * Mf + mtile*64;
    const float* vBase  = g_v  + (size_t)b * Nn * Dm + h*DHe;

    for (int n0 = 0; n0 < Nn; n0 += 32) {
        #pragma unroll
        for (int it = 0; it < 8; it++) {
            int j = it*256 + tid;
            int nn = j >> 6, cq = j & 63;
            kpc[nn][cq] = kpBase[(size_t)(n0+nn)*Mf + cq];
            vc [nn][cq] = vBase [(size_t)(n0+nn)*Dm + cq];
        }
        __syncthreads();
        #pragma unroll
        for (int nn = 0; nn < 32; nn++) {
            float4 kf = *(const float4*)&kpc[nn][ty*4];
            float4 vf = *(const float4*)&vc [nn][tx*4];
            float kr[4] = {kf.x,kf.y,kf.z,kf.w};
            float vr[4] = {vf.x,vf.y,vf.z,vf.w};
            #pragma unroll
            for (int i = 0; i < 4; i++)
                #pragma unroll
                for (int j = 0; j < 4; j++)
                    acc[i][j] += kr[i]*vr[j];
        }
        __syncthreads();
    }
    #pragma unroll
    for (int i = 0; i < 4; i++) {
        int m = mtile*64 + ty*4 + i;
        float* cp = g_ctx + (size_t)bh*Mf*DHe + m*DHe + tx*4;
        *(float4*)cp = make_float4(acc[i][0],acc[i][1],acc[i][2],acc[i][3]);
    }
}

// ---------------- attn out ----------------
__global__ __launch_bounds__(256)
void attnout_kernel()
{
    extern __shared__ float fsm[];
    float* ctxT  = fsm;                 // [64][260]
    float* ksum_s= fsm + 64*260;
    float* qps   = ksum_s + 256;

    const int ntile = blockIdx.x;
    const int bh    = blockIdx.y;
    const int b = bh >> 4, h = bh & 15;
    const int tid = threadIdx.x;

    for (int j = tid; j < Mf*DHe; j += 256) {
        int m = j >> 6, d = j & 63;
        ctxT[d*260 + m] = g_ctx[(size_t)bh*Mf*DHe + j];
    }
    ksum_s[tid] = g_ksum[bh*Mf + tid];
    __syncthreads();

    const int d   = tid & 63;
    const int tok = tid >> 6;
    const float4* ct4 = (const float4*)(ctxT + d*260);
    const float4* ks4 = (const float4*)ksum_s;

    for (int gIt = 0; gIt < 16; gIt++) {
        int nbase = ntile*64 + gIt*4;
        #pragma unroll
        for (int it = 0; it < 4; it++) {
            int j = it*256 + tid;
            int tk = j >> 8, mm = j & 255;
            qps[j] = g_qp[((size_t)bh*Nn + nbase + tk)*Mf + mm];
        }
        __syncthreads();

        const float4* qv4 = (const float4*)(qps + tok*256);
        float acc = 0.f, den = 0.f;
        #pragma unroll 8
        for (int mq = 0; mq < 64; mq++) {
            float4 qf = qv4[mq];
            float4 cf = ct4[mq];
            float4 kf = ks4[mq];
            acc += qf.x*cf.x + qf.y*cf.y + qf.z*cf.z + qf.w*cf.w;
            den += qf.x*kf.x + qf.y*kf.y + qf.z*kf.z + qf.w*kf.w;
        }
        int n = nbase + tok;
        g_attn[(size_t)(b*Nn + n)*Dm + h*DHe + d] = acc / den;
        __syncthreads();
    }
}

// ---------------- LayerNorm(a + b) * g + be ----------------
__global__ __launch_bounds__(256)
void ln_kernel(const float* __restrict__ A, const float* __restrict__ Bc,
               const float* __restrict__ g, const float* __restrict__ be,
               float* __restrict__ out)
{
    __shared__ float s1s[8], s2s[8], bc[2];
    const int row = blockIdx.x;
    const int tid = threadIdx.x;
    const int lane = tid & 31, wid = tid >> 5;

    const float4* a4 = (const float4*)(A  + (size_t)row*Dm);
    const float4* b4 = (const float4*)(Bc + (size_t)row*Dm);
    float4 va = a4[tid], vb = b4[tid];
    float4 v = make_float4(va.x+vb.x, va.y+vb.y, va.z+vb.z, va.w+vb.w);

    float s1 = v.x+v.y+v.z+v.w;
    float s2 = v.x*v.x+v.y*v.y+v.z*v.z+v.w*v.w;
    #pragma unroll
    for (int off = 16; off; off >>= 1) {
        s1 += __shfl_xor_sync(0xffffffffu, s1, off);
        s2 += __shfl_xor_sync(0xffffffffu, s2, off);
    }
    if (lane == 0) { s1s[wid] = s1; s2s[wid] = s2; }
    __syncthreads();
    if (tid == 0) {
        float S1 = 0.f, S2 = 0.f;
        #pragma unroll
        for (int i = 0; i < 8; i++) { S1 += s1s[i]; S2 += s2s[i]; }
        float mu = S1 * (1.f/Dm);
        float var = S2 * (1.f/Dm) - mu*mu;
        bc[0] = mu;
        bc[1] = rsqrtf(var + LNEPS);
    }
    __syncthreads();
    float mu = bc[0], rstd = bc[1];

    float4 gg = ((const float4*)g)[tid];
    float4 bb = ((const float4*)be)[tid];
    float4 o = make_float4((v.x-mu)*rstd*gg.x + bb.x,
                           (v.y-mu)*rstd*gg.y + bb.y,
                           (v.z-mu)*rstd*gg.z + bb.z,
                           (v.w-mu)*rstd*gg.w + bb.w);
    ((float4*)(out + (size_t)row*Dm))[tid] = o;
}

// ---------------- host ----------------
extern "C" void kernel_launch(void* const* d_in, const int* in_sizes, int n_in,
                              void* d_out, int out_size)
{
    const float* video = (const float*)d_in[0];
    const float* Wq    = (const float*)d_in[1];
    const float* bq    = (const float*)d_in[2];
    const float* Wk    = (const float*)d_in[3];
    const float* bk    = (const float*)d_in[4];
    const float* Wv    = (const float*)d_in[5];
    const float* bv    = (const float*)d_in[6];
    const float* Wo    = (const float*)d_in[7];
    const float* bo    = (const float*)d_in[8];
    const float* proj  = (const float*)d_in[9];
    const float* W1    = (const float*)d_in[10];
    const float* b1    = (const float*)d_in[11];
    const float* W2    = (const float*)d_in[12];
    const float* b2    = (const float*)d_in[13];
    const float* g2    = (const float*)d_in[14];
    const float* be2   = (const float*)d_in[15];
    const float* g3    = (const float*)d_in[16];
    const float* be3   = (const float*)d_in[17];
    float* out = (float*)d_out;

    float *q, *k, *v, *attn, *y, *x1, *ffh;
    cudaGetSymbolAddress((void**)&q,    g_q);
    cudaGetSymbolAddress((void**)&k,    g_k);
    cudaGetSymbolAddress((void**)&v,    g_v);
    cudaGetSymbolAddress((void**)&attn, g_attn);
    cudaGetSymbolAddress((void**)&y,    g_y);
    cudaGetSymbolAddress((void**)&x1,   g_x1);
    cudaGetSymbolAddress((void**)&ffh,  g_ffh);

    const int featSmem = (64*256 + 64 + 8 + 1) * 4;
    const int outSmem  = (64*260 + 256 + 4*256) * 4;
    cudaFuncSetAttribute(feat_q_kernel,  cudaFuncAttributeMaxDynamicSharedMemorySize, featSmem);
    cudaFuncSetAttribute(feat_kA_kernel, cudaFuncAttributeMaxDynamicSharedMemorySize, featSmem);
    cudaFuncSetAttribute(attnout_kernel, cudaFuncAttributeMaxDynamicSharedMemorySize, outSmem);
    cudaFuncSetAttribute(mma_gemm,       cudaFuncAttributeMaxDynamicSharedMemorySize, GEMM_SMEM);

    // 1. QKV projections (tf32 mma.sync)
    dim3 gQKV(Dm/GBN, Tt/GBM);   // 8 x 128
    mma_gemm<<<gQKV, 256, GEMM_SMEM>>>(video, Wq, bq, q, Tt, Dm, Dm, 0);
    mma_gemm<<<gQKV, 256, GEMM_SMEM>>>(video, Wk, bk, k, Tt, Dm, Dm, 0);
    mma_gemm<<<gQKV, 256, GEMM_SMEM>>>(video, Wv, bv, v, Tt, Dm, Dm, 0);

    // 2. feature maps
    init_kstab<<<1, 64>>>();
    int featBlocks = (BH*Nn) / FEAT_ROWS_PB;  // 4096
    feat_q_kernel <<<featBlocks, 256, featSmem>>>(proj);
    feat_kA_kernel<<<featBlocks, 256, featSmem>>>(proj);
    feat_kB_kernel<<<(BH*(size_t)Nn*Mf)/256, 256>>>();

    // 3. linear attention
    ksum_kernel<<<BH, 256>>>();
    ctx_kernel<<<dim3(BH, Mf/64), 256>>>();
    attnout_kernel<<<dim3(Nn/64, BH), 256, outSmem>>>();

    // 4. output projection + residual LN
    mma_gemm<<<gQKV, 256, GEMM_SMEM>>>(attn, Wo, bo, y, Tt, Dm, Dm, 0);
    ln_kernel<<<Tt, 256>>>(video, y, g2, be2, x1);

    // 5. FFN
    mma_gemm<<<dim3(DFFe/GBN, Tt/GBM), 256, GEMM_SMEM>>>(x1, W1, b1, ffh, Tt, DFFe, Dm, 1);
    mma_gemm<<<dim3(Dm/GBN, Tt/GBM), 256, GEMM_SMEM>>>(ffh, W2, b2, y, Tt, Dm, DFFe, 0);
    ln_kernel<<<Tt, 256>>>(x1, y, g3, be3, out);
}